// round 1
// baseline (speedup 1.0000x reference)
#include <cuda_runtime.h>
#include <cstdint>
#include <cstddef>

// Problem constants
#define CB    8
#define CIN   64
#define COUT  64
#define TDIM  512
#define FDIM  161

// Tiling
constexpr int TT  = 64;           // t-tile per block
constexpr int IC  = 8;            // CIN chunk
constexpr int NCH = CIN / IC;     // 8 chunks

// SMEM layout (floats)
constexpr int WS_BLK = 776;                 // 64*12 + 8 pad per (i,fl) block (bank spread)
constexpr int WS_BUF = IC * 2 * WS_BLK;     // 12416
constexpr int XS_ROW = 68;                  // 66 used + 2 pad
constexpr int XS_BUF = IC * 4 * XS_ROW;     // 2176
constexpr int SMEM_FLOATS = 2 * WS_BUF + 2 * XS_BUF;  // 29184 floats = 116736 B

// Transformed weights: wT[f][i][o][12]  (k=0..8 valid, 9..11 zero)
constexpr size_t WT_ELEMS = (size_t)FDIM * CIN * COUT * 12;
__device__ float g_wT[WT_ELEMS];

// ---------------------------------------------------------------------------
// Weight transform: kernel[o][i][f][3][3] -> wT[f][i][o][12]
// ---------------------------------------------------------------------------
__global__ void wtrans_kernel(const float* __restrict__ w)
{
    int idx = blockIdx.x * 256 + threadIdx.x;        // over F*CIN*COUT, o fastest
    int total = FDIM * CIN * COUT;
    if (idx >= total) return;
    int o = idx & 63;
    int r = idx >> 6;
    int i = r & 63;
    int f = r >> 6;
    const float* src = w + (((size_t)o * CIN + i) * FDIM + f) * 9;
    float* dst = g_wT + (size_t)idx * 12;
#pragma unroll
    for (int k = 0; k < 9; k++) dst[k] = src[k];
    dst[9] = 0.f; dst[10] = 0.f; dst[11] = 0.f;
}

// ---------------------------------------------------------------------------
// cp.async helpers
// ---------------------------------------------------------------------------
__device__ __forceinline__ void cp_async16(uint32_t s, const void* g)
{
    asm volatile("cp.async.ca.shared.global [%0], [%1], 16;\n" :: "r"(s), "l"(g));
}
__device__ __forceinline__ void cp_async4z(uint32_t s, const void* g, bool ok)
{
    int sz = ok ? 4 : 0;
    asm volatile("cp.async.ca.shared.global [%0], [%1], 4, %2;\n" :: "r"(s), "l"(g), "r"(sz));
}

// ---------------------------------------------------------------------------
// Main conv kernel
//   block: 256 threads -> out[b, 0:64, t0:t0+64, f0:f0+2]
//   thread (og,tg,fl): o = og*4+0..3, t = t0+tg*8+0..7, f = f0+fl
// ---------------------------------------------------------------------------
__global__ void __launch_bounds__(256, 1)
conv_kernel(const float* __restrict__ x,
            const float* __restrict__ bias,
            float* __restrict__ out)
{
    extern __shared__ float smem[];
    float* ws = smem;                 // 2 x WS_BUF
    float* xs = smem + 2 * WS_BUF;    // 2 x XS_BUF

    const int tid = threadIdx.x;
    const int fl  = tid & 1;
    const int tg  = (tid >> 1) & 7;
    const int og  = tid >> 4;
    const int f0  = blockIdx.x * 2;
    const int t0  = blockIdx.y * TT;
    const int b   = blockIdx.z;
    const int f   = f0 + fl;
    const int tl  = tg * 8;
    const int ob  = og * 4;

    const uint32_t smem_base = (uint32_t)__cvta_generic_to_shared(smem);
    const float* xb = x + (size_t)b * CIN * TDIM * FDIM;

    // ---- accumulators init with bias ----
    float acc[4][8];
#pragma unroll
    for (int oo = 0; oo < 4; oo++) {
        float bv = (f < FDIM) ? bias[(ob + oo) * FDIM + f] : 0.f;
#pragma unroll
        for (int rt = 0; rt < 8; rt++) acc[oo][rt] = bv;
    }

    // ---- prefetch of one chunk (weights + x halo tile) into buffer buf ----
    auto prefetch = [&](int c, int buf) {
        const int i0 = c * IC;
        // weights: 3072 float4, contiguous per (i,fl) block of 768 floats
        const uint32_t wdst0 = smem_base + (uint32_t)(buf * WS_BUF) * 4u;
#pragma unroll
        for (int j = 0; j < 12; j++) {
            int q   = j * 256 + tid;          // < 3072
            int blk = q / 192;                // i*2 + fl2
            int r   = q - blk * 192;          // float4 within block
            int ii  = blk >> 1;
            int fl2 = blk & 1;
            int ff  = min(f0 + fl2, FDIM - 1);
            const float* src = g_wT + (size_t)(ff * CIN + i0 + ii) * 768 + r * 4;
            uint32_t dst = wdst0 + (uint32_t)(blk * WS_BLK + r * 4) * 4u;
            cp_async16(dst, src);
        }
        // x tile: IC x 4(freq) x 66(t) with zero-fill halo, ff fastest for coalescing
        const uint32_t xdst0 = smem_base + (uint32_t)(2 * WS_BUF + buf * XS_BUF) * 4u;
        for (int e = tid; e < IC * 66 * 4; e += 256) {
            int ff  = e & 3;
            int rem = e >> 2;                 // i*66 + tt
            int ii  = rem / 66;
            int tt  = rem - ii * 66;
            int gt  = t0 - 1 + tt;
            int gf  = f0 - 1 + ff;
            bool ok = (gt >= 0) & (gt < TDIM) & (gf >= 0) & (gf < FDIM);
            const float* src = xb + ((size_t)(i0 + ii) * TDIM + (ok ? gt : 0)) * FDIM
                                  + (ok ? gf : 0);
            uint32_t dst = xdst0 + (uint32_t)((ii * 4 + ff) * XS_ROW + tt) * 4u;
            cp_async4z(dst, src, ok);
        }
    };

    prefetch(0, 0);
    asm volatile("cp.async.commit_group;\n");

    for (int c = 0; c < NCH; c++) {
        if (c + 1 < NCH) {
            prefetch(c + 1, (c + 1) & 1);
            asm volatile("cp.async.commit_group;\n");
            asm volatile("cp.async.wait_group 1;\n");
        } else {
            asm volatile("cp.async.wait_group 0;\n");
        }
        __syncthreads();

        const float* wsb = ws + (c & 1) * WS_BUF;
        const float* xsb = xs + (c & 1) * XS_BUF;

#pragma unroll 1
        for (int i = 0; i < IC; i++) {
            // x window: 10 t-positions x 3 freq offsets (vector LDS)
            float xv[10][3];
#pragma unroll
            for (int n = 0; n < 3; n++) {
                const float* row = xsb + (i * 4 + fl + n) * XS_ROW + tl;
                float4 a  = *reinterpret_cast<const float4*>(row);
                float4 b4 = *reinterpret_cast<const float4*>(row + 4);
                float2 c2 = *reinterpret_cast<const float2*>(row + 8);
                xv[0][n] = a.x;  xv[1][n] = a.y;  xv[2][n] = a.z;  xv[3][n] = a.w;
                xv[4][n] = b4.x; xv[5][n] = b4.y; xv[6][n] = b4.z; xv[7][n] = b4.w;
                xv[8][n] = c2.x; xv[9][n] = c2.y;
            }
#pragma unroll
            for (int oo = 0; oo < 4; oo++) {
                const float* wrow = wsb + (i * 2 + fl) * WS_BLK + (ob + oo) * 12;
                float4 w0 = *reinterpret_cast<const float4*>(wrow);
                float4 w1 = *reinterpret_cast<const float4*>(wrow + 4);
                float  w8 = wrow[8];
                float w[9] = {w0.x, w0.y, w0.z, w0.w, w1.x, w1.y, w1.z, w1.w, w8};
#pragma unroll
                for (int rt = 0; rt < 8; rt++) {
                    float s = acc[oo][rt];
#pragma unroll
                    for (int m = 0; m < 3; m++)
#pragma unroll
                        for (int n = 0; n < 3; n++)
                            s = fmaf(w[m * 3 + n], xv[rt + m][n], s);
                    acc[oo][rt] = s;
                }
            }
        }
        __syncthreads();
    }

    // ---- store ----
    if (f < FDIM) {
#pragma unroll
        for (int oo = 0; oo < 4; oo++) {
            float* op = out + (((size_t)b * COUT + ob + oo) * TDIM + (t0 + tl)) * FDIM + f;
#pragma unroll
            for (int rt = 0; rt < 8; rt++)
                op[(size_t)rt * FDIM] = acc[oo][rt];
        }
    }
}

// ---------------------------------------------------------------------------
// Launch
// ---------------------------------------------------------------------------
extern "C" void kernel_launch(void* const* d_in, const int* in_sizes, int n_in,
                              void* d_out, int out_size)
{
    const float* x    = (const float*)d_in[0];
    const float* w    = (const float*)d_in[1];
    const float* bias = (const float*)d_in[2];
    float* out        = (float*)d_out;

    cudaFuncSetAttribute(conv_kernel,
                         cudaFuncAttributeMaxDynamicSharedMemorySize,
                         SMEM_FLOATS * 4);

    int total = FDIM * CIN * COUT;
    wtrans_kernel<<<(total + 255) / 256, 256>>>(w);

    dim3 grid((FDIM + 1) / 2, TDIM / TT, CB);
    conv_kernel<<<grid, 256, SMEM_FLOATS * 4>>>(x, bias, out);
}